// round 15
// baseline (speedup 1.0000x reference)
#include <cuda_runtime.h>
#include <cuda_fp16.h>
#include <cstdint>
#include <cstddef>

#define NB   64
#define NIC  128
#define NOC  256
#define NHW  56
#define NDG  4
#define HW2  (NHW*NHW)

#define NTHREADS 128
#define BROWS 232                  // (2 out rows + 2 halo) x 58 w-positions

// ---------------- smem layout (dynamic, 106 KB -> 2 CTAs/SM) ----------------
#define SM_BH   0                  // 232 * 256 B = 59392
#define SM_A    59392              // 3 slots x 16 KB (A k-half slabs)
#define SMEM_TOTAL 108544

// Pre-swizzled fp16 weights, HALF-SLAB layout:
// per (d, octile, tap): [half(2)][oc(128)][128B swizzled] = 32 KB
__device__ __align__(16) __half g_w2[NDG * 2 * 9 * 16384];

// ---------------- ptx helpers (baseline ISA only) ----------------
__device__ __forceinline__ uint32_t smem_u32(const void* p) {
    uint32_t a;
    asm("{ .reg .u64 t; cvta.to.shared.u64 t, %1; cvt.u32.u64 %0, t; }"
        : "=r"(a) : "l"(p));
    return a;
}
__device__ __forceinline__ void ldsm_x4(uint32_t* r, uint32_t addr) {
    asm volatile("ldmatrix.sync.aligned.m8n8.x4.shared.b16 {%0,%1,%2,%3}, [%4];"
                 : "=r"(r[0]), "=r"(r[1]), "=r"(r[2]), "=r"(r[3]) : "r"(addr));
}
__device__ __forceinline__ void ldsm_x2(uint32_t* r, uint32_t addr) {
    asm volatile("ldmatrix.sync.aligned.m8n8.x2.shared.b16 {%0,%1}, [%2];"
                 : "=r"(r[0]), "=r"(r[1]) : "r"(addr));
}
__device__ __forceinline__ void cp_async16(uint32_t saddr, const void* gptr) {
    asm volatile("cp.async.cg.shared.global [%0], [%1], 16;"
                 :: "r"(saddr), "l"(gptr) : "memory");
}
#define CP_COMMIT() asm volatile("cp.async.commit_group;" ::: "memory")
#define CP_WAIT0()  asm volatile("cp.async.wait_group 0;" ::: "memory")

#define MMA_FP16(c, a, b)                                                     \
    asm volatile(                                                             \
        "mma.sync.aligned.m16n8k16.row.col.f32.f16.f16.f32 "                  \
        "{%0,%1,%2,%3},{%4,%5,%6,%7},{%8,%9},{%0,%1,%2,%3};"                  \
        : "+f"((c)[0]), "+f"((c)[1]), "+f"((c)[2]), "+f"((c)[3])              \
        : "r"((a)[0]), "r"((a)[1]), "r"((a)[2]), "r"((a)[3]),                 \
          "r"((b)[0]), "r"((b)[1]))

// ---------------------------------------------------------------------------
// Prep: masked weights -> fp16, half-slab swizzled image.
// byte = half*16384 + oc*128 + (((ic&63)*2) ^ ((oc&7)<<4)), half = ic>>6
// ---------------------------------------------------------------------------
__global__ void prep_weights_kernel(const float* __restrict__ base,
                                    const float* __restrict__ mask) {
    int e = blockIdx.x * blockDim.x + threadIdx.x;
    const int total = NDG * 2 * 9 * 128 * 128;
    if (e >= total) return;
    int ic  = e % 128;
    int t2  = e / 128;
    int oc  = t2 % 128;
    int t3  = t2 / 128;
    int tap = t3 % 9;
    int t4  = t3 / 9;
    int oct = t4 % 2;
    int d   = t4 / 2;

    float w = base[((size_t)(oct * 128 + oc) * 128 + ic) * 9 + tap] *
              mask[((size_t)d * 128 + ic) * 9 + tap];

    uint32_t byte = (uint32_t)((ic >> 6) * 16384 + oc * 128 +
                               (((ic & 63) * 2) ^ ((oc & 7) << 4)));
    size_t slab = (size_t)((d * 2 + oct) * 9 + tap) * 16384;
    g_w2[slab + (byte >> 1)] = __float2half(w);
}

// ---------------------------------------------------------------------------
// CTA = (row-pair hp, octile 128, b). 128 threads = 4 warps: 2 M-warps
// (M64) x 2 N-warps (1 output row, N=56). 2 CTAs/SM.
// ---------------------------------------------------------------------------
__global__ __launch_bounds__(NTHREADS, 2)
void adaconv_mma_kernel(const float* __restrict__ x,
                        const int*   __restrict__ label,
                        float*       __restrict__ out) {
    extern __shared__ char smem[];
    const uint32_t sb = smem_u32(smem);

    const int tid  = threadIdx.x;
    const int wid  = tid >> 5;
    const int lane = tid & 31;
    const int warp_m = wid & 1;       // oc tile of 64
    const int warp_n = wid >> 1;      // output row (0/1)

    const int hp  = blockIdx.x;       // 0..27
    const int oct = blockIdx.y;       // 0..1
    const int b   = blockIdx.z;       // 0..63
    const int h0  = hp * 2;
    const int rev = blockIdx.x & 1;

    int d = label[b];
    d = (d < 0) ? 0 : (d > NDG - 1 ? NDG - 1 : d);

    const float* __restrict__ xg = x + (size_t)b * NIC * HW2;
    const char* __restrict__ wbase =
        (const char*)(g_w2 + (size_t)((d * 2 + oct) * 9) * 16384);

    const int tap0 = rev ? 8 : 0;

    // ---- prologue: A(tap0).h0 -> slot0, A(tap0).h1 -> slot1 ----
    {
        const char* g0 = wbase + (size_t)tap0 * 32768;
#pragma unroll
        for (int j = 0; j < 8; ++j) {
            cp_async16(sb + SM_A + tid * 16 + j * 2048, g0 + tid * 16 + j * 2048);
            cp_async16(sb + SM_A + 16384 + tid * 16 + j * 2048,
                       g0 + 16384 + tid * 16 + j * 2048);
        }
        CP_COMMIT();
    }

    // ---- build B once: rows tid and tid+128 ----
#pragma unroll
    for (int itb = 0; itb < 2; ++itb) {
        int np = tid + itb * 128;
        if (np < BROWS) {
            const int rowl = np / 58;
            const int wq   = np - rowl * 58;
            const int h_in = h0 - 1 + rowl;
            const int w_in = wq - 1;
            const bool inb = (h_in >= 0 && h_in < NHW && w_in >= 0 && w_in < NHW);
            const float* __restrict__ xp = xg + (size_t)h_in * NHW + w_in;
            const uint32_t brow = (uint32_t)(np * 256);
            const uint32_t bx   = (uint32_t)((np & 7) << 4);
#pragma unroll 8
            for (int icp = 0; icp < 64; ++icp) {
                float v0 = 0.f, v1 = 0.f;
                if (inb) {
                    v0 = xp[(size_t)(icp * 2) * HW2];
                    v1 = xp[(size_t)(icp * 2 + 1) * HW2];
                }
                __half h0b = __float2half(v0);
                __half h1b = __float2half(v1);
                uint32_t hw = (uint32_t)__half_as_ushort(h0b) |
                              ((uint32_t)__half_as_ushort(h1b) << 16);
                uint32_t byte = brow + (((uint32_t)(icp * 4)) ^ bx);
                *(uint32_t*)(smem + SM_BH + byte) = hw;
            }
        }
    }

    float acc[4][7][4];
#pragma unroll
    for (int mt = 0; mt < 4; ++mt)
#pragma unroll
        for (int nt = 0; nt < 7; ++nt)
#pragma unroll
            for (int q = 0; q < 4; ++q) acc[mt][nt][q] = 0.f;

    // ---- hoisted per-warp invariants ----
    const int arow0    = warp_m * 64 + (lane & 15);
    const uint32_t akb = (uint32_t)((lane >> 4) << 4);
    uint32_t aoff[4], ax[4];
#pragma unroll
    for (int mt = 0; mt < 4; ++mt) {
        int r = arow0 + mt * 16;
        aoff[mt] = (uint32_t)(r * 128);
        ax[mt]   = (uint32_t)((r & 7) << 4);
    }
    const uint32_t l15  = (uint32_t)(lane & 15);
    const uint32_t l7   = (uint32_t)(lane & 7);
    const uint32_t akb2 = (uint32_t)(((lane >> 3) & 1) << 4);

    uint32_t ah[2][4][4], bh[2][7][2];

    int cbase = 0;
    for (int it = 0; it < 9; ++it) {
        const int tap  = rev ? 8 - it : it;
        const int ntap = rev ? tap - 1 : tap + 1;
        const int dh = tap / 3, dw = tap % 3;
        const int nb = (warp_n + dh) * 58 + dw;

        const uint32_t bxx   = (uint32_t)(((nb + (lane & 7)) & 7) << 4);
        const uint32_t boff0 = sb + SM_BH + (uint32_t)((nb + l15) * 256);
        const uint32_t boff1 = boff0 + 16 * 256;
        const uint32_t boff2 = boff0 + 32 * 256;
        const uint32_t boff6 = sb + SM_BH + (uint32_t)((nb + 48 + l7) * 256);

        const int s0 = cbase;
        const int s1 = (cbase + 1 == 3) ? 0 : cbase + 1;
        const int s2 = 3 - s0 - s1;
        const uint32_t a0 = sb + SM_A + (uint32_t)s0 * 16384;
        const uint32_t a1 = sb + SM_A + (uint32_t)s1 * 16384;

        CP_WAIT0();
        __syncthreads();

        if (it < 8) {   // A(ntap).h0 into free slot
            const char* gsrc = wbase + (size_t)ntap * 32768;
            uint32_t dst = sb + SM_A + (uint32_t)s2 * 16384;
#pragma unroll
            for (int j = 0; j < 8; ++j)
                cp_async16(dst + tid * 16 + j * 2048, gsrc + tid * 16 + j * 2048);
            CP_COMMIT();
        }

        auto la = [&](int mt, int s, uint32_t abase, int k) {
            uint32_t kbl = (uint32_t)((k & 3) * 32) + akb;
            ldsm_x4(ah[s][mt], abase + aoff[mt] + (kbl ^ ax[mt]));
        };
        auto lb4 = [&](int p, int s, int k) {
            uint32_t kb = (uint32_t)(k * 32) + akb;
            uint32_t addr = (p == 0 ? boff0 : (p == 1 ? boff1 : boff2)) + (kb ^ bxx);
            uint32_t t[4];
            ldsm_x4(t, addr);
            bh[s][2 * p][0] = t[0]; bh[s][2 * p][1] = t[2];
            bh[s][2 * p + 1][0] = t[1]; bh[s][2 * p + 1][1] = t[3];
        };
        auto lb2 = [&](int s, int k) {
            uint32_t kb2 = (uint32_t)(k * 32) + akb2;
            uint32_t t[2];
            ldsm_x2(t, boff6 + (kb2 ^ bxx));
            bh[s][6][0] = t[0]; bh[s][6][1] = t[1];
        };
        // round(k): 56 mma of buffer s, loads for k+1 interleaved
        auto round = [&](int k, uint32_t a_next, bool do_load) {
            const int s = k & 1, ns = s ^ 1;
            const int kn = k + 1;
            if (do_load) { la(0, ns, a_next, kn); la(1, ns, a_next, kn); }
            MMA_FP16(acc[0][0], ah[s][0], bh[s][0]);
            MMA_FP16(acc[0][1], ah[s][0], bh[s][1]);
            MMA_FP16(acc[0][2], ah[s][0], bh[s][2]);
            if (do_load) { la(2, ns, a_next, kn); la(3, ns, a_next, kn); }
            MMA_FP16(acc[0][3], ah[s][0], bh[s][3]);
            MMA_FP16(acc[0][4], ah[s][0], bh[s][4]);
            MMA_FP16(acc[0][5], ah[s][0], bh[s][5]);
            if (do_load) lb4(0, ns, kn);
            MMA_FP16(acc[0][6], ah[s][0], bh[s][6]);
            MMA_FP16(acc[1][0], ah[s][1], bh[s][0]);
            MMA_FP16(acc[1][1], ah[s][1], bh[s][1]);
            if (do_load) lb4(1, ns, kn);
            MMA_FP16(acc[1][2], ah[s][1], bh[s][2]);
            MMA_FP16(acc[1][3], ah[s][1], bh[s][3]);
            MMA_FP16(acc[1][4], ah[s][1], bh[s][4]);
            if (do_load) lb4(2, ns, kn);
            MMA_FP16(acc[1][5], ah[s][1], bh[s][5]);
            MMA_FP16(acc[1][6], ah[s][1], bh[s][6]);
            MMA_FP16(acc[2][0], ah[s][2], bh[s][0]);
            if (do_load) lb2(ns, kn);
            MMA_FP16(acc[2][1], ah[s][2], bh[s][1]);
            MMA_FP16(acc[2][2], ah[s][2], bh[s][2]);
            MMA_FP16(acc[2][3], ah[s][2], bh[s][3]);
            MMA_FP16(acc[2][4], ah[s][2], bh[s][4]);
            MMA_FP16(acc[2][5], ah[s][2], bh[s][5]);
            MMA_FP16(acc[2][6], ah[s][2], bh[s][6]);
            MMA_FP16(acc[3][0], ah[s][3], bh[s][0]);
            MMA_FP16(acc[3][1], ah[s][3], bh[s][1]);
            MMA_FP16(acc[3][2], ah[s][3], bh[s][2]);
            MMA_FP16(acc[3][3], ah[s][3], bh[s][3]);
            MMA_FP16(acc[3][4], ah[s][3], bh[s][4]);
            MMA_FP16(acc[3][5], ah[s][3], bh[s][5]);
            MMA_FP16(acc[3][6], ah[s][3], bh[s][6]);
        };

        // ---- k0..3 on slot s0 ----
        la(0, 0, a0, 0); la(1, 0, a0, 0); la(2, 0, a0, 0); la(3, 0, a0, 0);
        lb4(0, 0, 0); lb4(1, 0, 0); lb4(2, 0, 0); lb2(0, 0);
#pragma unroll
        for (int k = 0; k < 3; ++k) round(k, a0, true);
        round(3, a1, true);

        __syncthreads();
        if (it < 8) {   // A(ntap).h1 into dead slot s0
            const char* gsrc = wbase + (size_t)ntap * 32768 + 16384;
            uint32_t dst = sb + SM_A + (uint32_t)s0 * 16384;
#pragma unroll
            for (int j = 0; j < 8; ++j)
                cp_async16(dst + tid * 16 + j * 2048, gsrc + tid * 16 + j * 2048);
            CP_COMMIT();
        }

        // ---- k4..7 on slot s1 ----
#pragma unroll
        for (int k = 4; k < 7; ++k) round(k, a1, true);
        round(7, a1, false);

        cbase += 2;
        if (cbase >= 3) cbase -= 3;
    }

    // ---- epilogue ----
    const int h = h0 + warp_n;
    const int col0 = (lane & 3) * 2;
    const int r0 = lane >> 2;
#pragma unroll
    for (int mt = 0; mt < 4; ++mt) {
        int ocb = oct * 128 + warp_m * 64 + mt * 16;
        float* __restrict__ o0 = out + ((size_t)b * NOC + ocb + r0) * HW2 + (size_t)h * NHW;
        float* __restrict__ o1 = o0 + (size_t)8 * HW2;
#pragma unroll
        for (int nt = 0; nt < 7; ++nt) {
            int w = nt * 8 + col0;
            *(float2*)(o0 + w) = make_float2(acc[mt][nt][0], acc[mt][nt][1]);
            *(float2*)(o1 + w) = make_float2(acc[mt][nt][2], acc[mt][nt][3]);
        }
    }
}

// ---------------------------------------------------------------------------
extern "C" void kernel_launch(void* const* d_in, const int* in_sizes, int n_in,
                              void* d_out, int out_size) {
    const float* x     = nullptr;
    const int*   label = nullptr;
    const float* base  = nullptr;
    const float* mask  = nullptr;
    for (int i = 0; i < n_in; ++i) {
        switch (in_sizes[i]) {
            case 25690112: x     = (const float*)d_in[i]; break;
            case 64:       label = (const int*)  d_in[i]; break;
            case 294912:   base  = (const float*)d_in[i]; break;
            case 4608:     mask  = (const float*)d_in[i]; break;
            default: break;
        }
    }
    if (!x     && n_in > 0) x     = (const float*)d_in[0];
    if (!label && n_in > 1) label = (const int*)  d_in[1];
    if (!base  && n_in > 2) base  = (const float*)d_in[2];
    if (!mask  && n_in > 3) mask  = (const float*)d_in[3];

    float* out = (float*)d_out;

    {
        const int total = NDG * 2 * 9 * 128 * 128;
        prep_weights_kernel<<<(total + 255) / 256, 256>>>(base, mask);
    }
    cudaFuncSetAttribute(adaconv_mma_kernel,
                         cudaFuncAttributeMaxDynamicSharedMemorySize, SMEM_TOTAL);
    {
        dim3 grid(28, 2, NB);
        adaconv_mma_kernel<<<grid, NTHREADS, SMEM_TOTAL>>>(x, label, out);
    }
}